// round 17
// baseline (speedup 1.0000x reference)
#include <cuda_runtime.h>
#include <math.h>

namespace {

constexpr int EMBED     = 20;
constexpr int THREADS   = 256;   // conv CTA
constexpr int FEAT      = 560;
constexpr int BATCH_MAX = 16384;

typedef unsigned long long ull;

// ---------------- packed f32x2 helpers (Blackwell FFMA2) ----------------
__device__ __forceinline__ ull pack2(float a, float b) {
  ull r;
  asm("mov.b64 %0, {%1, %2};" : "=l"(r) : "f"(a), "f"(b));
  return r;
}
__device__ __forceinline__ void unpack2(ull v, float& a, float& b) {
  asm("mov.b64 {%0, %1}, %2;" : "=f"(a), "=f"(b) : "l"(v));
}
__device__ __forceinline__ ull fma2(ull a, ull b, ull c) {
  ull d;
  asm("fma.rn.f32x2 %0, %1, %2, %3;" : "=l"(d) : "l"(a), "l"(b), "l"(c));
  return d;
}

// ---------------- global scratch ----------------
__device__ float  g_feat[FEAT * BATCH_MAX];   // transposed [feat][B], fp32
__device__ float2 g_w1p[FEAT * 32];           // [i][colpair]=(W1[2c][i],W1[2c+1][i])
__device__ ull    g_wdup[56000];              // conv weights dup'd (w,w), *0.2 folded

// ull offsets per ksize (constexpr FUNCTION — device-safe, folds at compile time)
__host__ __device__ constexpr int woff(int kidx) {
  return (kidx == 0) ? 0 : (kidx == 1) ? 2240 : (kidx == 2) ? 8960
       : (kidx == 3) ? 20160 : 35840;
}

struct ConvParams {
  const float* seq[7];
  int B;
};
struct MlpParams {
  const float* lin1_b;
  const float* lin2_w;
  const float* lin2_b;
  float* out;
  int B;
};

// smem: x tile only, [c*L+l][33] float2 = (x_b, x_{b+32}); max L = 18
constexpr int CONV_SMEM_BYTES = EMBED * 18 * 33 * 8;   // 95040

// ====== CONV v3: conv_chunk2 + pre-dup'd ull weights (no pack MOVs) ======
template<int L, int K, int T0, int T1>
__device__ __forceinline__ void conv_chunk2(const ull* __restrict__ sXu,
                                            const ull* __restrict__ wd0,
                                            const ull* __restrict__ wd1,
                                            int lane, float (&mx)[4]) {
  constexpr int PAD = (K - 1) / 2;
  constexpr int XLO = (T0 - PAD > 0) ? (T0 - PAD) : 0;
  constexpr int XHI = (T1 + PAD < L) ? (T1 + PAD) : L;   // exclusive
  constexpr int NX  = XHI - XLO;
  constexpr int NT  = T1 - T0;
  ull a0[NT], a1[NT];
  #pragma unroll
  for (int t = 0; t < NT; ++t) { a0[t] = 0ULL; a1[t] = 0ULL; }
  for (int c = 0; c < EMBED; ++c) {
    ull xx[NX];
    #pragma unroll
    for (int l = 0; l < NX; ++l)
      xx[l] = sXu[(c * L + XLO + l) * 33 + lane];        // LDS.64 once
    ull w0[K], w1[K];
    #pragma unroll
    for (int j = 0; j < K; ++j) {
      w0[j] = __ldg(wd0 + c * K + j);                    // LDG.64, pre-dup'd
      w1[j] = __ldg(wd1 + c * K + j);
    }
    #pragma unroll
    for (int t = T0; t < T1; ++t) {
      #pragma unroll
      for (int j = 0; j < K; ++j) {
        const int xi = t + j - PAD;                      // compile-time pred
        if (xi >= 0 && xi < L) {
          a0[t - T0] = fma2(xx[xi - XLO], w0[j], a0[t - T0]);
          a1[t - T0] = fma2(xx[xi - XLO], w1[j], a1[t - T0]);
        }
      }
    }
  }
  #pragma unroll
  for (int t = 0; t < NT; ++t) {
    float a, b;
    unpack2(a0[t], a, b); mx[0] = fmaxf(mx[0], a); mx[1] = fmaxf(mx[1], b);
    unpack2(a1[t], a, b); mx[2] = fmaxf(mx[2], a); mx[3] = fmaxf(mx[3], b);
  }
}

template<int L, int K>
__device__ __forceinline__ void conv_all2(const ull* __restrict__ sXu,
                                          const ull* __restrict__ wd0,
                                          const ull* __restrict__ wd1,
                                          int lane, float (&mx)[4]) {
  if constexpr (L <= 6) {
    conv_chunk2<L, K, 0, L>(sXu, wd0, wd1, lane, mx);
  } else if constexpr (L <= 9) {
    constexpr int M = (L + 1) / 2;
    conv_chunk2<L, K, 0, M>(sXu, wd0, wd1, lane, mx);
    conv_chunk2<L, K, M, L>(sXu, wd0, wd1, lane, mx);
  } else if constexpr (L <= 12) {
    conv_chunk2<L, K, 0, 6>(sXu, wd0, wd1, lane, mx);
    conv_chunk2<L, K, 6, L>(sXu, wd0, wd1, lane, mx);
  } else {
    conv_chunk2<L, K, 0, 6>(sXu, wd0, wd1, lane, mx);
    conv_chunk2<L, K, 6, 12>(sXu, wd0, wd1, lane, mx);
    conv_chunk2<L, K, 12, L>(sXu, wd0, wd1, lane, mx);
  }
}

template<int L, int S>
__device__ void do_seq(const ConvParams& p, float2* sX2,
                       int tid, int lane, int w, int bbase) {
  // stage x paired (x_b, x_{b+32}); 0.2 scale folded into g_wdup
  const float* xg = p.seq[S];
  constexpr int CL = EMBED * L;
  for (int idx = tid; idx < CL * 32; idx += THREADS) {
    const int bp  = idx / CL;
    const int rem = idx - bp * CL;
    const int b0  = min(bbase + bp, p.B - 1);
    const int b1  = min(b0 + 32, p.B - 1);
    sX2[rem * 33 + bp] = make_float2(xg[(size_t)b0 * CL + rem],
                                     xg[(size_t)b1 * CL + rem]);
  }
  __syncthreads();
  const ull* sXu = (const ull*)sX2;
  const int bg0 = min(bbase + lane, p.B - 1);
  const int bg1 = min(bg0 + 32, p.B - 1);
  const int f0  = 2 * w;

  #pragma unroll
  for (int kidx = 0; kidx < 5; ++kidx) {
    constexpr int KS_[5] = {1, 3, 5, 7, 9};
    const int K = KS_[kidx];
    const ull* wd0 = g_wdup + woff(kidx) + (size_t)(S * 16 + f0) * EMBED * K;
    const ull* wd1 = wd0 + EMBED * K;
    float mx[4];
    #pragma unroll
    for (int i = 0; i < 4; ++i) mx[i] = 0.f;   // relu folded into init
    switch (kidx) {
      case 0: conv_all2<L, 1>(sXu, wd0, wd1, lane, mx); break;
      case 1: conv_all2<L, 3>(sXu, wd0, wd1, lane, mx); break;
      case 2: conv_all2<L, 5>(sXu, wd0, wd1, lane, mx); break;
      case 3: conv_all2<L, 7>(sXu, wd0, wd1, lane, mx); break;
      case 4: conv_all2<L, 9>(sXu, wd0, wd1, lane, mx); break;
    }
    const int featBase = S * 80 + kidx * 16;
    g_feat[(size_t)(featBase + f0)     * p.B + bg0] = mx[0];
    g_feat[(size_t)(featBase + f0)     * p.B + bg1] = mx[1];
    g_feat[(size_t)(featBase + f0 + 1) * p.B + bg0] = mx[2];
    g_feat[(size_t)(featBase + f0 + 1) * p.B + bg1] = mx[3];
  }
}

__global__ __launch_bounds__(THREADS, 2) void conv_kernel(ConvParams p) {
  extern __shared__ float smem[];
  float2* sX2 = (float2*)smem;
  const int tid   = threadIdx.x;
  const int lane  = tid & 31;
  const int w     = tid >> 5;          // warp -> filter pair (2w, 2w+1)
  const int bbase = blockIdx.x * 64;   // 64 batch per CTA (paired)
  switch (blockIdx.y) {
    case 0: do_seq<12, 0>(p, sX2, tid, lane, w, bbase); break;
    case 1: do_seq< 7, 1>(p, sX2, tid, lane, w, bbase); break;
    case 2: do_seq< 8, 2>(p, sX2, tid, lane, w, bbase); break;
    case 3: do_seq<16, 3>(p, sX2, tid, lane, w, bbase); break;
    case 4: do_seq< 6, 4>(p, sX2, tid, lane, w, bbase); break;
    case 5: do_seq< 7, 5>(p, sX2, tid, lane, w, bbase); break;
    case 6: do_seq<18, 6>(p, sX2, tid, lane, w, bbase); break;
  }
}

// ---------------- prep kernels ----------------
__global__ void prep_wdup_kernel(const float* __restrict__ w1,
                                 const float* __restrict__ w3,
                                 const float* __restrict__ w5,
                                 const float* __restrict__ w7,
                                 const float* __restrict__ w9) {
  const int idx = blockIdx.x * 256 + threadIdx.x;
  if (idx >= 56000) return;
  float v;
  if      (idx < woff(1)) v = w1[idx - woff(0)];
  else if (idx < woff(2)) v = w3[idx - woff(1)];
  else if (idx < woff(3)) v = w5[idx - woff(2)];
  else if (idx < woff(4)) v = w7[idx - woff(3)];
  else                    v = w9[idx - woff(4)];
  v *= 0.2f;
  g_wdup[idx] = pack2(v, v);
}

__global__ void prep_w1_kernel(const float* __restrict__ w1) {
  const int idx = blockIdx.x * 256 + threadIdx.x;
  if (idx < FEAT * 32) {
    const int i   = idx >> 5;
    const int col = idx & 31;
    g_w1p[idx] = make_float2(w1[(size_t)(2 * col) * FEAT + i],
                             w1[(size_t)(2 * col + 1) * FEAT + i]);
  }
}

// ====== MLP v9: v5 + longlong2 weight loads + 8-deep feature prefetch ====
constexpr int MTHREADS = 512;
constexpr int MLP_SMEM_BYTES = 2 * 128 * 65 * 4;   // 66560

__global__ __launch_bounds__(MTHREADS) void mlp_kernel(MlpParams p) {
  extern __shared__ float smem[];
  float* sP1 = smem;              // [128][65] h=1 partials
  float* sH  = smem + 128 * 65;   // [128][65] sigmoid outputs
  const int tid  = threadIdx.x;
  const int lane = tid & 31;
  const int wid  = tid >> 5;      // 0..15
  const int h    = wid >> 3;      // feature half
  const int g    = wid & 7;       // hidden col group (8 cols)
  const int bbase = blockIdx.x * 128;
  const bool full = (bbase + 128 <= p.B);

  ull acc[4][4];                  // [col pair][batch i]
  #pragma unroll
  for (int pp = 0; pp < 4; ++pp) {
    const ull bia = (h == 0)
      ? pack2(p.lin1_b[g * 8 + 2 * pp], p.lin1_b[g * 8 + 2 * pp + 1])
      : 0ULL;
    #pragma unroll
    for (int bi = 0; bi < 4; ++bi) acc[pp][bi] = bia;
  }

  const longlong2* wbase = (const longlong2*)(g_w1p);  // 8 longlong2 / feature
  const int i0 = h * 280;

  for (int oo = 0; oo < 280; oo += 8) {
    float4 fb[8];
    if (full) {
      #pragma unroll
      for (int k = 0; k < 8; ++k)
        fb[k] = __ldg((const float4*)(g_feat + (size_t)(i0 + oo + k) * p.B
                                      + bbase + lane * 4));
    } else {
      #pragma unroll
      for (int k = 0; k < 8; ++k) {
        float v[4];
        #pragma unroll
        for (int bi = 0; bi < 4; ++bi) {
          const int b = min(bbase + lane * 4 + bi, p.B - 1);
          v[bi] = g_feat[(size_t)(i0 + oo + k) * p.B + b];
        }
        fb[k] = make_float4(v[0], v[1], v[2], v[3]);
      }
    }
    #pragma unroll
    for (int k = 0; k < 8; ++k) {
      const int i = i0 + oo + k;
      const longlong2 wa = __ldg(wbase + i * 16 + g * 2);      // colpairs 4g,4g+1
      const longlong2 wb = __ldg(wbase + i * 16 + g * 2 + 1);  // colpairs 4g+2,4g+3
      const ull w0  = (ull)wa.x;
      const ull w1v = (ull)wa.y;
      const ull w2  = (ull)wb.x;
      const ull w3  = (ull)wb.y;
      const float fv[4] = {fb[k].x, fb[k].y, fb[k].z, fb[k].w};
      #pragma unroll
      for (int bi = 0; bi < 4; ++bi) {
        const ull ff = pack2(fv[bi], fv[bi]);
        acc[0][bi] = fma2(ff, w0, acc[0][bi]);
        acc[1][bi] = fma2(ff, w1v, acc[1][bi]);
        acc[2][bi] = fma2(ff, w2, acc[2][bi]);
        acc[3][bi] = fma2(ff, w3, acc[3][bi]);
      }
    }
  }

  if (h == 1) {
    #pragma unroll
    for (int bi = 0; bi < 4; ++bi)
      #pragma unroll
      for (int pp = 0; pp < 4; ++pp) {
        float a, bb; unpack2(acc[pp][bi], a, bb);
        sP1[(lane * 4 + bi) * 65 + g * 8 + 2 * pp]     = a;
        sP1[(lane * 4 + bi) * 65 + g * 8 + 2 * pp + 1] = bb;
      }
  }
  __syncthreads();
  if (h == 0) {
    #pragma unroll
    for (int bi = 0; bi < 4; ++bi)
      #pragma unroll
      for (int pp = 0; pp < 4; ++pp) {
        float a, bb; unpack2(acc[pp][bi], a, bb);
        a  += sP1[(lane * 4 + bi) * 65 + g * 8 + 2 * pp];
        bb += sP1[(lane * 4 + bi) * 65 + g * 8 + 2 * pp + 1];
        sH[(lane * 4 + bi) * 65 + g * 8 + 2 * pp]     = 1.f / (1.f + __expf(-a));
        sH[(lane * 4 + bi) * 65 + g * 8 + 2 * pp + 1] = 1.f / (1.f + __expf(-bb));
      }
  }
  __syncthreads();

  if (tid < 128) {
    const int bgo = bbase + tid;
    if (bgo < p.B) {
      float o = p.lin2_b[0];
      #pragma unroll
      for (int j = 0; j < 64; ++j)
        o = fmaf(sH[tid * 65 + j], __ldg(p.lin2_w + j), o);
      p.out[bgo] = o;
    }
  }
}

} // namespace

extern "C" void kernel_launch(void* const* d_in, const int* in_sizes, int n_in,
                              void* d_out, int out_size) {
  ConvParams cp;
  for (int i = 0; i < 7; ++i) cp.seq[i] = (const float*)d_in[i];
  cp.B = out_size;

  MlpParams mp;
  mp.lin1_b = (const float*)d_in[13];
  mp.lin2_w = (const float*)d_in[14];
  mp.lin2_b = (const float*)d_in[15];
  mp.out = (float*)d_out;
  mp.B   = out_size;

  static bool attr_set = false;
  if (!attr_set) {
    cudaFuncSetAttribute(conv_kernel,
                         cudaFuncAttributeMaxDynamicSharedMemorySize, CONV_SMEM_BYTES);
    cudaFuncSetAttribute(mlp_kernel,
                         cudaFuncAttributeMaxDynamicSharedMemorySize, MLP_SMEM_BYTES);
    attr_set = true;
  }

  const int tiles64  = (cp.B + 63) / 64;
  const int tiles128 = (cp.B + 127) / 128;
  prep_wdup_kernel<<<(56000 + 255) / 256, 256>>>(
      (const float*)d_in[7], (const float*)d_in[8], (const float*)d_in[9],
      (const float*)d_in[10], (const float*)d_in[11]);
  prep_w1_kernel<<<(FEAT * 32 + 255) / 256, 256>>>((const float*)d_in[12]);
  dim3 cgrid(tiles64, 7);
  conv_kernel<<<cgrid, THREADS, CONV_SMEM_BYTES>>>(cp);
  mlp_kernel<<<tiles128, MTHREADS, MLP_SMEM_BYTES>>>(mp);
}